// round 7
// baseline (speedup 1.0000x reference)
#include <cuda_runtime.h>
#include <cuda_fp16.h>

#define BATCH   256
#define IN_DIM  65536
#define OUT_DIM 65536

#define NT_TR  1024   // transpose tiles per half: 512 i-tiles x 2 b-tiles(64)
#define NT_CF  256
#define NT_IX  512
#define NT_MN  2048   // main tiles per half: 32 neurons x 128 batches

// ---------------- device scratch ----------------------------------------
__device__ float4 g_coef[OUT_DIM];                             // 1 MB
__device__ __align__(16) __half g_xth[(size_t)IN_DIM * BATCH]; // 32 MB
__device__ int    g_idx[2 * OUT_DIM];                          // 512 KB

// ---------------- transpose tile: 128 inputs x 64 batches, 256 thr ------
__device__ __forceinline__ void transpose_tile(float* t /*[4*64*33]*/,
                                               const float* __restrict__ x,
                                               int it, int b0, int tid) {
    int i0 = it * 128;
    int tx = tid & 7, ty = tid >> 3;

    const float4* r0 = (const float4*)(x + (size_t)(b0 + ty)      * IN_DIM + i0);
    const float4* r1 = (const float4*)(x + (size_t)(b0 + 32 + ty) * IN_DIM + i0);
    float4 v0[4], v1[4];
    #pragma unroll
    for (int h = 0; h < 4; h++) {
        v0[h] = __ldcs(r0 + tx + 8 * h);
        v1[h] = __ldcs(r1 + tx + 8 * h);
    }
    #pragma unroll
    for (int h = 0; h < 4; h++) {
        float* th = t + h * (64 * 33);
        th[(ty     )*33 + tx*4+0]=v0[h].x; th[(ty     )*33 + tx*4+1]=v0[h].y;
        th[(ty     )*33 + tx*4+2]=v0[h].z; th[(ty     )*33 + tx*4+3]=v0[h].w;
        th[(ty + 32)*33 + tx*4+0]=v1[h].x; th[(ty + 32)*33 + tx*4+1]=v1[h].y;
        th[(ty + 32)*33 + tx*4+2]=v1[h].z; th[(ty + 32)*33 + tx*4+3]=v1[h].w;
    }
    __syncthreads();
    #pragma unroll
    for (int h = 0; h < 4; h++) {
        const float* th = t + h * (64 * 33);
        union { uint4 u; __half2 hh[4]; } pk;
        #pragma unroll
        for (int k = 0; k < 4; k++)
            pk.hh[k] = __floats2half2_rn(th[(8*tx + 2*k)*33 + ty],
                                         th[(8*tx + 2*k + 1)*33 + ty]);
        *(uint4*)(g_xth + (size_t)(i0 + 32*h + ty) * BATCH + b0 + 8*tx) = pk.u;
    }
}

// ---------------- main tile: 32 neurons x 128 batches, 256 thr ----------
// 8 warps x 4 neurons. Half-warp row trick: one LDG.128 covers the 256B
// half-row of TWO neurons (lanes 0-15 -> n, 16-31 -> n+1). 4 LDGs/thread.
__device__ __forceinline__ void main_tile(float* s /*[128*32]*/,
                                          float* __restrict__ out,
                                          int id, int hf, int tid) {
    int ob = id * 32;
    int w = tid >> 5, l = tid & 31;
    int h = l >> 4, j = l & 15;
    int nb = ob + w * 4;

    const char* base = (const char*)g_xth;
    unsigned off = (unsigned)hf * 256u + 16u * (unsigned)j;
    unsigned oa0 = (unsigned)__ldg(&g_idx[nb + h])               * 512u + off;
    unsigned ob0 = (unsigned)__ldg(&g_idx[OUT_DIM + nb + h])     * 512u + off;
    unsigned oa1 = (unsigned)__ldg(&g_idx[nb + 2 + h])           * 512u + off;
    unsigned ob1 = (unsigned)__ldg(&g_idx[OUT_DIM + nb + 2 + h]) * 512u + off;

    union { uint4 u; __half2 hh[4]; } A0, B0, A1, B1;
    A0.u = *(const uint4*)(base + oa0);
    B0.u = *(const uint4*)(base + ob0);
    A1.u = *(const uint4*)(base + oa1);
    B1.u = *(const uint4*)(base + ob1);

    float4 c0 = __ldg(&g_coef[nb + h]);
    float4 c1 = __ldg(&g_coef[nb + 2 + h]);

    int nl0 = w * 4 + h;           // local neuron col for pair 0
    int nl1 = nl0 + 2;
    int col0 = (nl0 + 2 * j) & 31; // store bank = (h + 2j + const): bijective
    int col1 = (nl1 + 2 * j) & 31;
    int bbase = 8 * j;
    #pragma unroll
    for (int k2 = 0; k2 < 4; k2++) {
        float2 a = __half22float2(A0.hh[k2]);
        float2 b = __half22float2(B0.hh[k2]);
        int bb = bbase + 2 * k2;
        s[bb * 32 + col0]       = fmaf(fmaf(c0.w, b.x, c0.y), a.x, fmaf(c0.z, b.x, c0.x));
        s[(bb + 1) * 32 + col0] = fmaf(fmaf(c0.w, b.y, c0.y), a.y, fmaf(c0.z, b.y, c0.x));
    }
    #pragma unroll
    for (int k2 = 0; k2 < 4; k2++) {
        float2 a = __half22float2(A1.hh[k2]);
        float2 b = __half22float2(B1.hh[k2]);
        int bb = bbase + 2 * k2;
        s[bb * 32 + col1]       = fmaf(fmaf(c1.w, b.x, c1.y), a.x, fmaf(c1.z, b.x, c1.x));
        s[(bb + 1) * 32 + col1] = fmaf(fmaf(c1.w, b.y, c1.y), a.y, fmaf(c1.z, b.y, c1.x));
    }
    __syncthreads();

    // warp w writes batch rows 16w..16w+15, 128B-coalesced streaming stores
    #pragma unroll
    for (int k = 0; k < 16; k++) {
        int bb = w * 16 + k;
        __stcs(out + (size_t)(hf * 128 + bb) * OUT_DIM + ob + l,
               s[bb * 32 + ((l + 2 * (bb >> 3)) & 31)]);
    }
}

// ---------------- coef tile ---------------------------------------------
__device__ __forceinline__ void coef_tile(const float* __restrict__ wts, int o) {
    float p[16];
    const float4* w4 = (const float4*)(wts + (size_t)o * 16);
    float4 q0 = w4[0], q1 = w4[1], q2 = w4[2], q3 = w4[3];
    p[0]=q0.x; p[1]=q0.y; p[2]=q0.z; p[3]=q0.w;
    p[4]=q1.x; p[5]=q1.y; p[6]=q1.z; p[7]=q1.w;
    p[8]=q2.x; p[9]=q2.y; p[10]=q2.z; p[11]=q2.w;
    p[12]=q3.x; p[13]=q3.y; p[14]=q3.z; p[15]=q3.w;
    float m = p[0];
    #pragma unroll
    for (int i = 1; i < 16; i++) m = fmaxf(m, p[i]);
    float s = 0.f;
    #pragma unroll
    for (int i = 0; i < 16; i++) { p[i] = __expf(p[i] - m); s += p[i]; }
    float inv = 1.0f / s;
    #pragma unroll
    for (int i = 0; i < 16; i++) p[i] *= inv;
    float4 c;
    c.x = p[8]+p[9]+p[10]+p[11]+p[12]+p[13]+p[14]+p[15];
    c.y = p[2]+p[3]+p[6]+p[7]-p[8]-p[9]-p[12]-p[13];
    c.z = p[4]+p[5]+p[6]+p[7]-p[8]-p[9]-p[10]-p[11];
    c.w = p[1]-p[2]-p[4]-2.f*p[6]-p[7]+p[8]+2.f*p[9]+p[11]+p[13]-p[14];
    g_coef[o] = c;
}

// ---------------- K1: transpose half 0 + coef + idx ---------------------
__global__ __launch_bounds__(256) void k1_kernel(const float* __restrict__ x,
                                                 const float* __restrict__ wts,
                                                 const void*  __restrict__ idxraw) {
    __shared__ __align__(16) float t[4 * 64 * 33];
    int bx = blockIdx.x, tid = threadIdx.x;
    if (bx < NT_TR) {
        transpose_tile(t, x, bx >> 1, (bx & 1) * 64, tid);
    } else if (bx < NT_TR + NT_CF) {
        coef_tile(wts, (bx - NT_TR) * 256 + tid);
    } else {
        __shared__ int s64;
        if (tid == 0) {
            const long long* p = (const long long*)idxraw;
            int is64 = 1;
            #pragma unroll 1
            for (int jq = 0; jq < 64; jq++) {
                long long v = p[jq];
                if (v < 0 || v >= IN_DIM) { is64 = 0; break; }
            }
            s64 = is64;
        }
        __syncthreads();
        int i = (bx - NT_TR - NT_CF) * 256 + tid;
        g_idx[i] = s64 ? (int)((const long long*)idxraw)[i]
                       : ((const int*)idxraw)[i];
    }
}

// ---------------- K2: transpose half 1 overlapped with main half 0 ------
__global__ __launch_bounds__(256) void k2_kernel(const float* __restrict__ x,
                                                 float* __restrict__ out) {
    __shared__ __align__(16) float t[4 * 64 * 33];   // also covers main's 16KB
    int bx = blockIdx.x, tid = threadIdx.x;
    if (bx < NT_TR) transpose_tile(t, x, bx >> 1, 128 + (bx & 1) * 64, tid);
    else            main_tile(t, out, bx - NT_TR, 0, tid);
}

// ---------------- K3: main half 1 ---------------------------------------
__global__ __launch_bounds__(256) void k3_kernel(float* __restrict__ out) {
    __shared__ __align__(16) float s[128 * 32];      // 16 KB
    main_tile(s, out, blockIdx.x, 1, threadIdx.x);
}

// ---------------- launch ------------------------------------------------
extern "C" void kernel_launch(void* const* d_in, const int* in_sizes, int n_in,
                              void* d_out, int out_size) {
    const float* x   = (const float*)d_in[0];
    const float* wts = (const float*)d_in[1];
    const void*  idx = d_in[2];
    float* out = (float*)d_out;

    k1_kernel<<<NT_TR + NT_CF + NT_IX, 256>>>(x, wts, idx);
    k2_kernel<<<NT_TR + NT_MN, 256>>>(x, out);
    k3_kernel<<<NT_MN, 256>>>(out);
}